// round 2
// baseline (speedup 1.0000x reference)
#include <cuda_runtime.h>
#include <math.h>

#define NUSR 80000
#define NPRD 40000
#define NE   160000
#define DMODEL 256
#define NH 4
#define HD 64
#define QKVW 768   // [q | kt | vt]

// ---------------- scratch (static device arrays; no allocation) ----------------
__device__ float g_qkv_u[(size_t)NUSR * QKVW];
__device__ float g_qkv_p[(size_t)NPRD * QKVW];
__device__ float g_xu[(size_t)NUSR * DMODEL];
__device__ float g_xp[(size_t)NPRD * DMODEL];
__device__ float g_agg_u[(size_t)NUSR * DMODEL];
__device__ float g_agg_p[(size_t)NPRD * DMODEL];
__device__ float g_elog[(size_t)NE * NH];
__device__ int   g_csr_p[NE];
__device__ int   g_csr_u[NE];
__device__ int   g_deg_p[NPRD];
__device__ int   g_deg_u[NUSR];
__device__ int   g_off_p[NPRD + 1];
__device__ int   g_off_u[NUSR + 1];
__device__ int   g_cur_p[NPRD];
__device__ int   g_cur_u[NUSR];
__device__ float g_wcat[2][DMODEL * QKVW];  // per node type: fused [Wq | Wk@arel | Wv@mrel]
__device__ float g_bcat[2][QKVW];

__device__ __forceinline__ float geluf(float x) { return x * normcdff(x); }

// ---------------- CSR build ----------------
__global__ void k_zero_csr() {
    int i = blockIdx.x * blockDim.x + threadIdx.x;
    int st = gridDim.x * blockDim.x;
    for (int j = i; j < NUSR; j += st) { g_deg_u[j] = 0; g_cur_u[j] = 0; }
    for (int j = i; j < NPRD; j += st) { g_deg_p[j] = 0; g_cur_p[j] = 0; }
}

__global__ void k_hist(const int* __restrict__ esrc, const int* __restrict__ edst) {
    int i = blockIdx.x * blockDim.x + threadIdx.x;
    if (i < NE) {
        atomicAdd(&g_deg_p[edst[i]], 1);
        atomicAdd(&g_deg_u[esrc[i]], 1);
    }
}

// single-block exclusive scan (n <= ~100k), out has n+1 entries
__global__ void k_scan(const int* __restrict__ in, int* __restrict__ out, int n) {
    __shared__ int sh[1024];
    const int T = 1024;
    int t = threadIdx.x;
    int chunk = (n + T - 1) / T;
    int b = t * chunk;
    int e = min(b + chunk, n);
    int s = 0;
    for (int i = b; i < e; i++) s += in[i];
    sh[t] = s;
    __syncthreads();
    for (int off = 1; off < T; off <<= 1) {
        int v = (t >= off) ? sh[t - off] : 0;
        __syncthreads();
        sh[t] += v;
        __syncthreads();
    }
    int run = (t == 0) ? 0 : sh[t - 1];
    for (int i = b; i < e; i++) { out[i] = run; run += in[i]; }
    if (t == T - 1) out[n] = run;
}

__global__ void k_scatter(const int* __restrict__ esrc, const int* __restrict__ edst) {
    int i = blockIdx.x * blockDim.x + threadIdx.x;
    if (i >= NE) return;
    int s = esrc[i], d = edst[i];
    int pp = g_off_p[d] + atomicAdd(&g_cur_p[d], 1);
    g_csr_p[pp] = s;                 // product-dst CSR: neighbor = user src
    int pu = g_off_u[s] + atomicAdd(&g_cur_u[s], 1);
    g_csr_u[pu] = d;                 // user-dst CSR: neighbor = product src
}

// ---------------- fused weight build ----------------
// g_wcat[t] = [ Wq[l,t] | Wk[l,t]@blockdiag(arel[l,t]) | Wv[l,t]@blockdiag(mrel[l,t]) ]
__global__ void k_fuse(const float* __restrict__ Wq, const float* __restrict__ bq,
                       const float* __restrict__ Wk, const float* __restrict__ bk,
                       const float* __restrict__ Wv, const float* __restrict__ bv,
                       const float* __restrict__ arel, const float* __restrict__ mrel, int l) {
    int tot = 2 * 257 * QKVW;   // row 256 = bias row
    for (int idx = blockIdx.x * blockDim.x + threadIdx.x; idx < tot; idx += gridDim.x * blockDim.x) {
        int t = idx / (257 * QKVW);
        int r = idx % (257 * QKVW);
        int i = r / QKVW;
        int j = r % QKVW;
        int lt = l * 2 + t;
        float out;
        if (j < 256) {
            out = (i < 256) ? Wq[((size_t)(lt * 256 + i)) * 256 + j] : bq[lt * 256 + j];
        } else {
            int jj = j - 256;
            const float *W, *bb, *rel;
            if (jj < 256) { W = Wk; bb = bk; rel = arel; }
            else { jj -= 256; W = Wv; bb = bv; rel = mrel; }
            int h = jj / HD, ee = jj % HD;
            const float* rp = rel + ((size_t)(lt * NH + h)) * HD * HD + ee; // stride HD over d
            float s = 0.f;
            if (i < 256) {
                const float* wp = W + ((size_t)(lt * 256 + i)) * 256 + h * HD;
                #pragma unroll 8
                for (int d = 0; d < HD; d++) s += wp[d] * rp[d * HD];
            } else {
                const float* bp = bb + lt * 256 + h * HD;
                #pragma unroll 8
                for (int d = 0; d < HD; d++) s += bp[d] * rp[d * HD];
            }
            out = s;
        }
        if (i < 256) g_wcat[t][i * QKVW + j] = out;
        else         g_bcat[t][j] = out;
    }
}

// ---------------- tiled SGEMM with fused gelu(A) + bias + skip-blend epilogue ----------------
#define BM 64
#define BN 64
#define BK 16

__global__ __launch_bounds__(256) void k_gemm(
    const float* __restrict__ A, const int* __restrict__ rowmap, int geluA,
    const float* __restrict__ B, const float* __restrict__ bias,
    float* __restrict__ C, int ldc, int M, int N, int K,
    const float* __restrict__ Xold, const int* __restrict__ rowmapOld,
    const float* __restrict__ skipPtr)
{
    __shared__ float As[BK][BM + 4];
    __shared__ float Bs[BK][BN + 4];
    int tid = threadIdx.x;
    int tx = tid & 15, ty = tid >> 4;
    int row0 = blockIdx.y * BM, col0 = blockIdx.x * BN;

    int lm = tid >> 2;            // 0..63  (A tile row)
    int lk = (tid & 3) * 4;       // 0,4,8,12 (A tile k quad)
    int arow = row0 + lm;
    int amrow = rowmap ? rowmap[arow] : arow;
    const float* Aptr = A + (size_t)amrow * K;

    int lkb = tid >> 4;           // 0..15 (B tile row)
    int lnb = (tid & 15) * 4;     // B tile col quad

    float acc[4][4] = {};

    for (int k0 = 0; k0 < K; k0 += BK) {
        float4 av = *(const float4*)(Aptr + k0 + lk);
        if (geluA) { av.x = geluf(av.x); av.y = geluf(av.y); av.z = geluf(av.z); av.w = geluf(av.w); }
        As[lk + 0][lm] = av.x; As[lk + 1][lm] = av.y; As[lk + 2][lm] = av.z; As[lk + 3][lm] = av.w;
        *(float4*)&Bs[lkb][lnb] = *(const float4*)(B + (size_t)(k0 + lkb) * N + col0 + lnb);
        __syncthreads();
        #pragma unroll
        for (int kk = 0; kk < BK; kk++) {
            float4 a4 = *(const float4*)&As[kk][ty * 4];
            float4 b4 = *(const float4*)&Bs[kk][tx * 4];
            float a[4] = {a4.x, a4.y, a4.z, a4.w};
            float b[4] = {b4.x, b4.y, b4.z, b4.w};
            #pragma unroll
            for (int i = 0; i < 4; i++)
                #pragma unroll
                for (int j = 0; j < 4; j++)
                    acc[i][j] = fmaf(a[i], b[j], acc[i][j]);
        }
        __syncthreads();
    }

    float beta = 0.f, ombeta = 0.f;
    if (skipPtr) { float sk = *skipPtr; beta = 1.f / (1.f + expf(-sk)); ombeta = 1.f - beta; }
    int c = col0 + tx * 4;
    float4 bi = *(const float4*)(bias + c);
    #pragma unroll
    for (int i = 0; i < 4; i++) {
        int r = row0 + ty * 4 + i;
        float4 v;
        v.x = acc[i][0] + bi.x; v.y = acc[i][1] + bi.y;
        v.z = acc[i][2] + bi.z; v.w = acc[i][3] + bi.w;
        if (skipPtr) {
            int ro = rowmapOld ? rowmapOld[r] : r;
            float4 xo = *(const float4*)(Xold + (size_t)ro * DMODEL + c);
            v.x = beta * v.x + ombeta * xo.x;
            v.y = beta * v.y + ombeta * xo.y;
            v.z = beta * v.z + ombeta * xo.z;
            v.w = beta * v.w + ombeta * xo.w;
        }
        *(float4*)&C[(size_t)r * ldc + c] = v;
    }
}

// ---------------- per-dst-node attention (one warp per node, no atomics) ----------------
__global__ void k_attend(const float* __restrict__ qkv_dst, const float* __restrict__ qkv_src,
                         const int* __restrict__ offs, const int* __restrict__ csr,
                         int n, const float* __restrict__ prelp, float* __restrict__ agg)
{
    int warp = (blockIdx.x * blockDim.x + threadIdx.x) >> 5;
    int lane = threadIdx.x & 31;
    if (warp >= n) return;

    const float* q = qkv_dst + (size_t)warp * QKVW;
    float qv[8];
    #pragma unroll
    for (int k = 0; k < 8; k++) qv[k] = q[lane + 32 * k];

    const float inv_sqrt_d = 0.125f;  // 1/sqrt(64)
    float pr0 = prelp[0] * inv_sqrt_d, pr1 = prelp[1] * inv_sqrt_d;
    float pr2 = prelp[2] * inv_sqrt_d, pr3 = prelp[3] * inv_sqrt_d;

    int beg = offs[warp], end = offs[warp + 1];
    float m0 = -1e30f, m1 = -1e30f, m2 = -1e30f, m3 = -1e30f;

    // pass 1: logits + max, store raw logits
    for (int e = beg; e < end; e++) {
        int s = csr[e];
        const float* kt = qkv_src + (size_t)s * QKVW + 256;
        float p0 = 0.f, p1 = 0.f, p2 = 0.f, p3 = 0.f;
        #pragma unroll
        for (int k = 0; k < 8; k++) {
            float t = qv[k] * kt[lane + 32 * k];
            if (k < 2) p0 += t; else if (k < 4) p1 += t; else if (k < 6) p2 += t; else p3 += t;
        }
        #pragma unroll
        for (int off = 16; off; off >>= 1) {
            p0 += __shfl_xor_sync(0xffffffffu, p0, off);
            p1 += __shfl_xor_sync(0xffffffffu, p1, off);
            p2 += __shfl_xor_sync(0xffffffffu, p2, off);
            p3 += __shfl_xor_sync(0xffffffffu, p3, off);
        }
        p0 *= pr0; p1 *= pr1; p2 *= pr2; p3 *= pr3;
        m0 = fmaxf(m0, p0); m1 = fmaxf(m1, p1);
        m2 = fmaxf(m2, p2); m3 = fmaxf(m3, p3);
        if (lane == 0) *(float4*)&g_elog[(size_t)e * 4] = make_float4(p0, p1, p2, p3);
    }

    // pass 2: exp, denom, weighted aggregation (divide once at the end)
    float s0 = 0.f, s1 = 0.f, s2 = 0.f, s3 = 0.f;
    float acc[8] = {0.f, 0.f, 0.f, 0.f, 0.f, 0.f, 0.f, 0.f};
    for (int e = beg; e < end; e++) {
        int s = csr[e];
        float4 lg = *(const float4*)&g_elog[(size_t)e * 4];
        float e0 = __expf(lg.x - m0), e1 = __expf(lg.y - m1);
        float e2 = __expf(lg.z - m2), e3 = __expf(lg.w - m3);
        s0 += e0; s1 += e1; s2 += e2; s3 += e3;
        const float* vt = qkv_src + (size_t)s * QKVW + 512;
        #pragma unroll
        for (int k = 0; k < 8; k++) {
            float ee = (k < 2) ? e0 : (k < 4) ? e1 : (k < 6) ? e2 : e3;
            acc[k] = fmaf(ee, vt[lane + 32 * k], acc[k]);
        }
    }
    float i0 = 1.f / (s0 + 1e-16f), i1 = 1.f / (s1 + 1e-16f);
    float i2 = 1.f / (s2 + 1e-16f), i3 = 1.f / (s3 + 1e-16f);
    float* o = agg + (size_t)warp * DMODEL;
    #pragma unroll
    for (int k = 0; k < 8; k++) {
        float inv = (k < 2) ? i0 : (k < 4) ? i1 : (k < 6) ? i2 : i3;
        o[lane + 32 * k] = acc[k] * inv;
    }
}

__global__ void k_gelu_inplace(float* __restrict__ x, int n) {
    int i = blockIdx.x * blockDim.x + threadIdx.x;
    int st = gridDim.x * blockDim.x;
    for (int j = i; j < n; j += st) x[j] = geluf(x[j]);
}

// ---------------- host orchestration ----------------
extern "C" void kernel_launch(void* const* d_in, const int* in_sizes, int n_in,
                              void* d_out, int out_size) {
    const int*   user_ids  = (const int*)d_in[0];
    const float* x_product = (const float*)d_in[1];
    const int*   edge_src  = (const int*)d_in[2];
    const int*   edge_dst  = (const int*)d_in[3];
    const float* user_emb  = (const float*)d_in[4];
    const float* Wk   = (const float*)d_in[5];
    const float* bk   = (const float*)d_in[6];
    const float* Wq   = (const float*)d_in[7];
    const float* bq   = (const float*)d_in[8];
    const float* Wv   = (const float*)d_in[9];
    const float* bv   = (const float*)d_in[10];
    const float* Wout = (const float*)d_in[11];
    const float* bout = (const float*)d_in[12];
    const float* skip = (const float*)d_in[13];
    const float* arel = (const float*)d_in[14];
    const float* mrel = (const float*)d_in[15];
    const float* prel = (const float*)d_in[16];

    float* out_xu = (float*)d_out;
    float* out_xp = out_xu + (size_t)NUSR * DMODEL;

    float *qkv_u, *qkv_p, *xu, *xp, *agg_u, *agg_p, *wcat, *bcat;
    int *csr_p, *csr_u, *off_p, *off_u, *deg_p, *deg_u;
    cudaGetSymbolAddress((void**)&qkv_u, g_qkv_u);
    cudaGetSymbolAddress((void**)&qkv_p, g_qkv_p);
    cudaGetSymbolAddress((void**)&xu, g_xu);
    cudaGetSymbolAddress((void**)&xp, g_xp);
    cudaGetSymbolAddress((void**)&agg_u, g_agg_u);
    cudaGetSymbolAddress((void**)&agg_p, g_agg_p);
    cudaGetSymbolAddress((void**)&wcat, g_wcat);
    cudaGetSymbolAddress((void**)&bcat, g_bcat);
    cudaGetSymbolAddress((void**)&csr_p, g_csr_p);
    cudaGetSymbolAddress((void**)&csr_u, g_csr_u);
    cudaGetSymbolAddress((void**)&off_p, g_off_p);
    cudaGetSymbolAddress((void**)&off_u, g_off_u);
    cudaGetSymbolAddress((void**)&deg_p, g_deg_p);
    cudaGetSymbolAddress((void**)&deg_u, g_deg_u);

    // ---- CSR build (both directions) ----
    k_zero_csr<<<256, 256>>>();
    k_hist<<<(NE + 255) / 256, 256>>>(edge_src, edge_dst);
    k_scan<<<1, 1024>>>(deg_p, off_p, NPRD);
    k_scan<<<1, 1024>>>(deg_u, off_u, NUSR);
    k_scatter<<<(NE + 255) / 256, 256>>>(edge_src, edge_dst);

    for (int l = 0; l < 2; l++) {
        k_fuse<<<1024, 256>>>(Wq, bq, Wk, bk, Wv, bv, arel, mrel, l);

        const float* Au  = (l == 0) ? user_emb : xu;
        const int*   rmu = (l == 0) ? user_ids : nullptr;
        k_gemm<<<dim3(QKVW / BN, NUSR / BM), 256>>>(
            Au, rmu, 0, wcat, bcat, qkv_u, QKVW, NUSR, QKVW, DMODEL,
            nullptr, nullptr, nullptr);

        const float* Ap = (l == 0) ? x_product : xp;
        k_gemm<<<dim3(QKVW / BN, NPRD / BM), 256>>>(
            Ap, nullptr, 0, wcat + DMODEL * QKVW, bcat + QKVW, qkv_p, QKVW, NPRD, QKVW, DMODEL,
            nullptr, nullptr, nullptr);

        // rel 0: user -> product (dst = product)
        k_attend<<<(NPRD * 32 + 255) / 256, 256>>>(
            qkv_p, qkv_u, off_p, csr_p, NPRD, prel + (l * 2 + 0) * NH, agg_p);
        // rel 1: product -> user (dst = user)
        k_attend<<<(NUSR * 32 + 255) / 256, 256>>>(
            qkv_u, qkv_p, off_u, csr_u, NUSR, prel + (l * 2 + 1) * NH, agg_u);

        // out GEMM product (dst_t = 1)
        float* Cp = (l == 0) ? xp : out_xp;
        const float* Xop = (l == 0) ? x_product : xp;
        k_gemm<<<dim3(DMODEL / BN, NPRD / BM), 256>>>(
            agg_p, nullptr, 1,
            Wout + (size_t)(l * 2 + 1) * DMODEL * DMODEL, bout + (l * 2 + 1) * DMODEL,
            Cp, DMODEL, NPRD, DMODEL, DMODEL,
            Xop, nullptr, skip + (l * 2 + 1));

        // out GEMM user (dst_t = 0)
        float* Cu = (l == 0) ? xu : out_xu;
        const float* Xou = (l == 0) ? user_emb : xu;
        const int*   rmo = (l == 0) ? user_ids : nullptr;
        k_gemm<<<dim3(DMODEL / BN, NUSR / BM), 256>>>(
            agg_u, nullptr, 1,
            Wout + (size_t)(l * 2 + 0) * DMODEL * DMODEL, bout + (l * 2 + 0) * DMODEL,
            Cu, DMODEL, NUSR, DMODEL, DMODEL,
            Xou, rmo, skip + (l * 2 + 0));

        if (l == 0) {
            k_gelu_inplace<<<2048, 256>>>(xu, NUSR * DMODEL);
            k_gelu_inplace<<<2048, 256>>>(xp, NPRD * DMODEL);
        }
    }
}

// round 3
// speedup vs baseline: 1.9452x; 1.9452x over previous
#include <cuda_runtime.h>
#include <math.h>

#define NUSR 80000
#define NPRD 40000
#define NE   160000
#define DMODEL 256
#define NH 4
#define HD 64
#define QKVW 768   // [q | kt | vt]

// ---------------- scratch (static device arrays; no allocation) ----------------
__device__ float g_qkv_u[(size_t)NUSR * QKVW];
__device__ float g_qkv_p[(size_t)NPRD * QKVW];
__device__ float g_xu[(size_t)NUSR * DMODEL];
__device__ float g_xp[(size_t)NPRD * DMODEL];
__device__ float g_agg_u[(size_t)NUSR * DMODEL];
__device__ float g_agg_p[(size_t)NPRD * DMODEL];
__device__ float g_elog[(size_t)NE * NH];
__device__ int   g_csr_p[NE];
__device__ int   g_csr_u[NE];
__device__ int   g_deg_p[NPRD];
__device__ int   g_deg_u[NUSR];
__device__ int   g_off_p[NPRD + 1];
__device__ int   g_off_u[NUSR + 1];
__device__ int   g_cur_p[NPRD];
__device__ int   g_cur_u[NUSR];
__device__ int   g_bsum[256];
__device__ float g_wcat[2][DMODEL * QKVW];  // per node type: fused [Wq | Wk@arel | Wv@mrel]
__device__ float g_bcat[2][QKVW];

__device__ __forceinline__ float geluf(float x) { return x * normcdff(x); }

// packed fp32x2 helpers (Blackwell FFMA2 path, PTX-only)
__device__ __forceinline__ unsigned long long pack2(float lo, float hi) {
    unsigned long long r;
    asm("mov.b64 %0, {%1, %2};" : "=l"(r) : "r"(__float_as_uint(lo)), "r"(__float_as_uint(hi)));
    return r;
}
__device__ __forceinline__ unsigned long long ffma2(unsigned long long a, unsigned long long b,
                                                    unsigned long long c) {
    unsigned long long d;
    asm("fma.rn.f32x2 %0, %1, %2, %3;" : "=l"(d) : "l"(a), "l"(b), "l"(c));
    return d;
}

// ---------------- CSR build ----------------
__global__ void k_zero_csr() {
    int i = blockIdx.x * blockDim.x + threadIdx.x;
    int st = gridDim.x * blockDim.x;
    for (int j = i; j < NUSR; j += st) { g_deg_u[j] = 0; g_cur_u[j] = 0; }
    for (int j = i; j < NPRD; j += st) { g_deg_p[j] = 0; g_cur_p[j] = 0; }
}

__global__ void k_hist(const int* __restrict__ esrc, const int* __restrict__ edst) {
    int i = blockIdx.x * blockDim.x + threadIdx.x;
    if (i < NE) {
        atomicAdd(&g_deg_p[edst[i]], 1);
        atomicAdd(&g_deg_u[esrc[i]], 1);
    }
}

// ---- multi-block exclusive scan (3 stages); total is always NE ----
#define SCH 1024
__global__ void k_bsum(const int* __restrict__ in, int n, int* __restrict__ bsum) {
    __shared__ int sh[256];
    int b = blockIdx.x, t = threadIdx.x;
    int base = b * SCH + t * 4;
    int s = 0;
    #pragma unroll
    for (int j = 0; j < 4; j++) { int i = base + j; if (i < n) s += in[i]; }
    sh[t] = s; __syncthreads();
    #pragma unroll
    for (int off = 128; off; off >>= 1) { if (t < off) sh[t] += sh[t + off]; __syncthreads(); }
    if (t == 0) bsum[b] = sh[0];
}

__global__ void k_scan_bsum(int* __restrict__ bsum, int nb) {
    __shared__ int sh[256];
    int t = threadIdx.x;
    int v = (t < nb) ? bsum[t] : 0;
    sh[t] = v; __syncthreads();
    for (int off = 1; off < 256; off <<= 1) {
        int u = (t >= off) ? sh[t - off] : 0; __syncthreads();
        sh[t] += u; __syncthreads();
    }
    if (t < nb) bsum[t] = sh[t] - v;   // exclusive
}

__global__ void k_scan_out(const int* __restrict__ in, int n, const int* __restrict__ bsum,
                           int* __restrict__ out) {
    __shared__ int sh[256];
    int b = blockIdx.x, t = threadIdx.x;
    int base = b * SCH + t * 4;
    int v[4]; int s = 0;
    #pragma unroll
    for (int j = 0; j < 4; j++) { int i = base + j; v[j] = (i < n) ? in[i] : 0; s += v[j]; }
    sh[t] = s; __syncthreads();
    int mine = s;
    for (int off = 1; off < 256; off <<= 1) {
        int u = (t >= off) ? sh[t - off] : 0; __syncthreads();
        sh[t] += u; __syncthreads();
    }
    int run = bsum[b] + sh[t] - mine;
    #pragma unroll
    for (int j = 0; j < 4; j++) { int i = base + j; if (i < n) out[i] = run; run += v[j]; }
    if (b == 0 && t == 0) out[n] = NE;   // degree sums always total NE
}

__global__ void k_scatter(const int* __restrict__ esrc, const int* __restrict__ edst) {
    int i = blockIdx.x * blockDim.x + threadIdx.x;
    if (i >= NE) return;
    int s = esrc[i], d = edst[i];
    int pp = g_off_p[d] + atomicAdd(&g_cur_p[d], 1);
    g_csr_p[pp] = s;
    int pu = g_off_u[s] + atomicAdd(&g_cur_u[s], 1);
    g_csr_u[pu] = d;
}

// ---------------- fused weight build ----------------
__global__ void k_fuse(const float* __restrict__ Wq, const float* __restrict__ bq,
                       const float* __restrict__ Wk, const float* __restrict__ bk,
                       const float* __restrict__ Wv, const float* __restrict__ bv,
                       const float* __restrict__ arel, const float* __restrict__ mrel, int l) {
    int tot = 2 * 257 * QKVW;
    for (int idx = blockIdx.x * blockDim.x + threadIdx.x; idx < tot; idx += gridDim.x * blockDim.x) {
        int t = idx / (257 * QKVW);
        int r = idx % (257 * QKVW);
        int i = r / QKVW;
        int j = r % QKVW;
        int lt = l * 2 + t;
        float out;
        if (j < 256) {
            out = (i < 256) ? Wq[((size_t)(lt * 256 + i)) * 256 + j] : bq[lt * 256 + j];
        } else {
            int jj = j - 256;
            const float *W, *bb, *rel;
            if (jj < 256) { W = Wk; bb = bk; rel = arel; }
            else { jj -= 256; W = Wv; bb = bv; rel = mrel; }
            int h = jj / HD, ee = jj % HD;
            const float* rp = rel + ((size_t)(lt * NH + h)) * HD * HD + ee;
            float s = 0.f;
            if (i < 256) {
                const float* wp = W + ((size_t)(lt * 256 + i)) * 256 + h * HD;
                #pragma unroll 8
                for (int d = 0; d < HD; d++) s += wp[d] * rp[d * HD];
            } else {
                const float* bp = bb + lt * 256 + h * HD;
                #pragma unroll 8
                for (int d = 0; d < HD; d++) s += bp[d] * rp[d * HD];
            }
            out = s;
        }
        if (i < 256) g_wcat[t][i * QKVW + j] = out;
        else         g_bcat[t][j] = out;
    }
}

// ---------------- 64x128 SGEMM, 8x8 microtile, packed f32x2 FMA ----------------
#define BM 64
#define BN 128
#define BK 16
#define GT 128   // threads per block

__global__ __launch_bounds__(GT) void k_gemm(
    const float* __restrict__ A, const int* __restrict__ rowmap, int geluA,
    const float* __restrict__ B, const float* __restrict__ bias,
    float* __restrict__ C, int ldc, int M, int N, int K,
    const float* __restrict__ Xold, const int* __restrict__ rowmapOld,
    const float* __restrict__ skipPtr)
{
    __shared__ float As[BK][BM + 4];    // [16][68]
    __shared__ float Bs[BK][BN + 8];    // [16][136]

    int tid = threadIdx.x;
    int tx = tid & 15;          // 0..15 : N
    int ty = tid >> 4;          // 0..7  : M
    int row0 = blockIdx.y * BM, col0 = blockIdx.x * BN;
    int ty8 = ty * 8, tx8 = tx * 8;

    // --- A global load mapping: 2 x float4 per thread per k-tile ---
    int rA = tid >> 2;                  // 0..31, second row = rA+32
    int kq = (tid & 3) * 4;             // k offset within tile
    int gr0 = row0 + rA, gr1 = row0 + rA + 32;
    if (rowmap) { gr0 = rowmap[gr0]; gr1 = rowmap[gr1]; }
    const float* pA0 = A + (size_t)gr0 * K + kq;
    const float* pA1 = A + (size_t)gr1 * K + kq;

    // --- B global load mapping: 4 x float4 per thread per k-tile ---
    int colB = (tid & 31) * 4;
    int kB = tid >> 5;                  // 0..3, rows kB + {0,4,8,12}
    const float* pB = B + (size_t)kB * N + col0 + colB;

    unsigned long long acc[8][4];
    unsigned long long z = pack2(0.f, 0.f);
    #pragma unroll
    for (int i = 0; i < 8; i++)
        #pragma unroll
        for (int j = 0; j < 4; j++) acc[i][j] = z;

    float4 a0v, a1v, b0v, b1v, b2v, b3v;

    // prologue: load tile 0
    a0v = *(const float4*)(pA0);
    a1v = *(const float4*)(pA1);
    if (geluA) {
        a0v.x = geluf(a0v.x); a0v.y = geluf(a0v.y); a0v.z = geluf(a0v.z); a0v.w = geluf(a0v.w);
        a1v.x = geluf(a1v.x); a1v.y = geluf(a1v.y); a1v.z = geluf(a1v.z); a1v.w = geluf(a1v.w);
    }
    b0v = *(const float4*)(pB);
    b1v = *(const float4*)(pB + (size_t)4 * N);
    b2v = *(const float4*)(pB + (size_t)8 * N);
    b3v = *(const float4*)(pB + (size_t)12 * N);

    const int NT = K / BK;
    for (int kt = 0; kt < NT; kt++) {
        // stage current regs -> smem
        As[kq + 0][rA] = a0v.x; As[kq + 1][rA] = a0v.y; As[kq + 2][rA] = a0v.z; As[kq + 3][rA] = a0v.w;
        As[kq + 0][rA + 32] = a1v.x; As[kq + 1][rA + 32] = a1v.y;
        As[kq + 2][rA + 32] = a1v.z; As[kq + 3][rA + 32] = a1v.w;
        *(float4*)&Bs[kB + 0][colB] = b0v;
        *(float4*)&Bs[kB + 4][colB] = b1v;
        *(float4*)&Bs[kB + 8][colB] = b2v;
        *(float4*)&Bs[kB + 12][colB] = b3v;
        __syncthreads();

        // prefetch next tile
        if (kt + 1 < NT) {
            int k0 = (kt + 1) * BK;
            a0v = *(const float4*)(pA0 + k0);
            a1v = *(const float4*)(pA1 + k0);
            if (geluA) {
                a0v.x = geluf(a0v.x); a0v.y = geluf(a0v.y); a0v.z = geluf(a0v.z); a0v.w = geluf(a0v.w);
                a1v.x = geluf(a1v.x); a1v.y = geluf(a1v.y); a1v.z = geluf(a1v.z); a1v.w = geluf(a1v.w);
            }
            const float* pBk = pB + (size_t)k0 * N;
            b0v = *(const float4*)(pBk);
            b1v = *(const float4*)(pBk + (size_t)4 * N);
            b2v = *(const float4*)(pBk + (size_t)8 * N);
            b3v = *(const float4*)(pBk + (size_t)12 * N);
        }

        #pragma unroll
        for (int kk = 0; kk < BK; kk++) {
            float4 af0 = *(const float4*)&As[kk][ty8];
            float4 af1 = *(const float4*)&As[kk][ty8 + 4];
            ulonglong2 bq0 = *(const ulonglong2*)&Bs[kk][tx8];
            ulonglong2 bq1 = *(const ulonglong2*)&Bs[kk][tx8 + 4];
            unsigned long long ad[8];
            ad[0] = pack2(af0.x, af0.x); ad[1] = pack2(af0.y, af0.y);
            ad[2] = pack2(af0.z, af0.z); ad[3] = pack2(af0.w, af0.w);
            ad[4] = pack2(af1.x, af1.x); ad[5] = pack2(af1.y, af1.y);
            ad[6] = pack2(af1.z, af1.z); ad[7] = pack2(af1.w, af1.w);
            unsigned long long bb[4] = { bq0.x, bq0.y, bq1.x, bq1.y };
            #pragma unroll
            for (int i = 0; i < 8; i++)
                #pragma unroll
                for (int j = 0; j < 4; j++)
                    acc[i][j] = ffma2(ad[i], bb[j], acc[i][j]);
        }
        __syncthreads();
    }

    // ---- epilogue ----
    float beta = 0.f, ombeta = 0.f;
    if (skipPtr) { float sk = *skipPtr; beta = 1.f / (1.f + expf(-sk)); ombeta = 1.f - beta; }
    int c = col0 + tx8;
    float4 bi0 = *(const float4*)(bias + c);
    float4 bi1 = *(const float4*)(bias + c + 4);
    union U { unsigned long long u; float2 f; };
    #pragma unroll
    for (int i = 0; i < 8; i++) {
        int r = row0 + ty8 + i;
        U u0, u1, u2, u3;
        u0.u = acc[i][0]; u1.u = acc[i][1]; u2.u = acc[i][2]; u3.u = acc[i][3];
        float4 v0, v1;
        v0.x = u0.f.x + bi0.x; v0.y = u0.f.y + bi0.y;
        v0.z = u1.f.x + bi0.z; v0.w = u1.f.y + bi0.w;
        v1.x = u2.f.x + bi1.x; v1.y = u2.f.y + bi1.y;
        v1.z = u3.f.x + bi1.z; v1.w = u3.f.y + bi1.w;
        if (skipPtr) {
            int ro = rowmapOld ? rowmapOld[r] : r;
            const float* xop = Xold + (size_t)ro * DMODEL + c;
            float4 xo0 = *(const float4*)(xop);
            float4 xo1 = *(const float4*)(xop + 4);
            v0.x = beta * v0.x + ombeta * xo0.x; v0.y = beta * v0.y + ombeta * xo0.y;
            v0.z = beta * v0.z + ombeta * xo0.z; v0.w = beta * v0.w + ombeta * xo0.w;
            v1.x = beta * v1.x + ombeta * xo1.x; v1.y = beta * v1.y + ombeta * xo1.y;
            v1.z = beta * v1.z + ombeta * xo1.z; v1.w = beta * v1.w + ombeta * xo1.w;
        }
        *(float4*)&C[(size_t)r * ldc + c] = v0;
        *(float4*)&C[(size_t)r * ldc + c + 4] = v1;
    }
}

// ---------------- per-dst-node attention (one warp per node, no atomics) ----------------
__global__ void k_attend(const float* __restrict__ qkv_dst, const float* __restrict__ qkv_src,
                         const int* __restrict__ offs, const int* __restrict__ csr,
                         int n, const float* __restrict__ prelp, float* __restrict__ agg)
{
    int warp = (blockIdx.x * blockDim.x + threadIdx.x) >> 5;
    int lane = threadIdx.x & 31;
    if (warp >= n) return;

    const float* q = qkv_dst + (size_t)warp * QKVW;
    float qv[8];
    #pragma unroll
    for (int k = 0; k < 8; k++) qv[k] = q[lane + 32 * k];

    const float inv_sqrt_d = 0.125f;
    float pr0 = prelp[0] * inv_sqrt_d, pr1 = prelp[1] * inv_sqrt_d;
    float pr2 = prelp[2] * inv_sqrt_d, pr3 = prelp[3] * inv_sqrt_d;

    int beg = offs[warp], end = offs[warp + 1];
    float m0 = -1e30f, m1 = -1e30f, m2 = -1e30f, m3 = -1e30f;

    for (int e = beg; e < end; e++) {
        int s = csr[e];
        const float* kt = qkv_src + (size_t)s * QKVW + 256;
        float p0 = 0.f, p1 = 0.f, p2 = 0.f, p3 = 0.f;
        #pragma unroll
        for (int k = 0; k < 8; k++) {
            float t = qv[k] * kt[lane + 32 * k];
            if (k < 2) p0 += t; else if (k < 4) p1 += t; else if (k < 6) p2 += t; else p3 += t;
        }
        #pragma unroll
        for (int off = 16; off; off >>= 1) {
            p0 += __shfl_xor_sync(0xffffffffu, p0, off);
            p1 += __shfl_xor_sync(0xffffffffu, p1, off);
            p2 += __shfl_xor_sync(0xffffffffu, p2, off);
            p3 += __shfl_xor_sync(0xffffffffu, p3, off);
        }
        p0 *= pr0; p1 *= pr1; p2 *= pr2; p3 *= pr3;
        m0 = fmaxf(m0, p0); m1 = fmaxf(m1, p1);
        m2 = fmaxf(m2, p2); m3 = fmaxf(m3, p3);
        if (lane == 0) *(float4*)&g_elog[(size_t)e * 4] = make_float4(p0, p1, p2, p3);
    }

    float s0 = 0.f, s1 = 0.f, s2 = 0.f, s3 = 0.f;
    float acc[8] = {0.f, 0.f, 0.f, 0.f, 0.f, 0.f, 0.f, 0.f};
    for (int e = beg; e < end; e++) {
        int s = csr[e];
        float4 lg = *(const float4*)&g_elog[(size_t)e * 4];
        float e0 = __expf(lg.x - m0), e1 = __expf(lg.y - m1);
        float e2 = __expf(lg.z - m2), e3 = __expf(lg.w - m3);
        s0 += e0; s1 += e1; s2 += e2; s3 += e3;
        const float* vt = qkv_src + (size_t)s * QKVW + 512;
        #pragma unroll
        for (int k = 0; k < 8; k++) {
            float ee = (k < 2) ? e0 : (k < 4) ? e1 : (k < 6) ? e2 : e3;
            acc[k] = fmaf(ee, vt[lane + 32 * k], acc[k]);
        }
    }
    float i0 = 1.f / (s0 + 1e-16f), i1 = 1.f / (s1 + 1e-16f);
    float i2 = 1.f / (s2 + 1e-16f), i3 = 1.f / (s3 + 1e-16f);
    float* o = agg + (size_t)warp * DMODEL;
    #pragma unroll
    for (int k = 0; k < 8; k++) {
        float inv = (k < 2) ? i0 : (k < 4) ? i1 : (k < 6) ? i2 : i3;
        o[lane + 32 * k] = acc[k] * inv;
    }
}

__global__ void k_gelu_inplace(float* __restrict__ x, int n) {
    int i = blockIdx.x * blockDim.x + threadIdx.x;
    int st = gridDim.x * blockDim.x;
    for (int j = i; j < n; j += st) x[j] = geluf(x[j]);
}

// ---------------- host orchestration ----------------
extern "C" void kernel_launch(void* const* d_in, const int* in_sizes, int n_in,
                              void* d_out, int out_size) {
    const int*   user_ids  = (const int*)d_in[0];
    const float* x_product = (const float*)d_in[1];
    const int*   edge_src  = (const int*)d_in[2];
    const int*   edge_dst  = (const int*)d_in[3];
    const float* user_emb  = (const float*)d_in[4];
    const float* Wk   = (const float*)d_in[5];
    const float* bk   = (const float*)d_in[6];
    const float* Wq   = (const float*)d_in[7];
    const float* bq   = (const float*)d_in[8];
    const float* Wv   = (const float*)d_in[9];
    const float* bv   = (const float*)d_in[10];
    const float* Wout = (const float*)d_in[11];
    const float* bout = (const float*)d_in[12];
    const float* skip = (const float*)d_in[13];
    const float* arel = (const float*)d_in[14];
    const float* mrel = (const float*)d_in[15];
    const float* prel = (const float*)d_in[16];

    float* out_xu = (float*)d_out;
    float* out_xp = out_xu + (size_t)NUSR * DMODEL;

    float *qkv_u, *qkv_p, *xu, *xp, *agg_u, *agg_p, *wcat, *bcat;
    int *csr_p, *csr_u, *off_p, *off_u, *deg_p, *deg_u, *bsum;
    cudaGetSymbolAddress((void**)&qkv_u, g_qkv_u);
    cudaGetSymbolAddress((void**)&qkv_p, g_qkv_p);
    cudaGetSymbolAddress((void**)&xu, g_xu);
    cudaGetSymbolAddress((void**)&xp, g_xp);
    cudaGetSymbolAddress((void**)&agg_u, g_agg_u);
    cudaGetSymbolAddress((void**)&agg_p, g_agg_p);
    cudaGetSymbolAddress((void**)&wcat, g_wcat);
    cudaGetSymbolAddress((void**)&bcat, g_bcat);
    cudaGetSymbolAddress((void**)&csr_p, g_csr_p);
    cudaGetSymbolAddress((void**)&csr_u, g_csr_u);
    cudaGetSymbolAddress((void**)&off_p, g_off_p);
    cudaGetSymbolAddress((void**)&off_u, g_off_u);
    cudaGetSymbolAddress((void**)&deg_p, g_deg_p);
    cudaGetSymbolAddress((void**)&deg_u, g_deg_u);
    cudaGetSymbolAddress((void**)&bsum, g_bsum);

    // ---- CSR build (both directions) ----
    k_zero_csr<<<256, 256>>>();
    k_hist<<<(NE + 255) / 256, 256>>>(edge_src, edge_dst);
    int nbP = (NPRD + SCH - 1) / SCH, nbU = (NUSR + SCH - 1) / SCH;
    k_bsum<<<nbP, 256>>>(deg_p, NPRD, bsum);
    k_scan_bsum<<<1, 256>>>(bsum, nbP);
    k_scan_out<<<nbP, 256>>>(deg_p, NPRD, bsum, off_p);
    k_bsum<<<nbU, 256>>>(deg_u, NUSR, bsum);
    k_scan_bsum<<<1, 256>>>(bsum, nbU);
    k_scan_out<<<nbU, 256>>>(deg_u, NUSR, bsum, off_u);
    k_scatter<<<(NE + 255) / 256, 256>>>(edge_src, edge_dst);

    for (int l = 0; l < 2; l++) {
        k_fuse<<<1024, 256>>>(Wq, bq, Wk, bk, Wv, bv, arel, mrel, l);

        const float* Au  = (l == 0) ? user_emb : xu;
        const int*   rmu = (l == 0) ? user_ids : nullptr;
        k_gemm<<<dim3(QKVW / BN, NUSR / BM), GT>>>(
            Au, rmu, 0, wcat, bcat, qkv_u, QKVW, NUSR, QKVW, DMODEL,
            nullptr, nullptr, nullptr);

        const float* Ap = (l == 0) ? x_product : xp;
        k_gemm<<<dim3(QKVW / BN, NPRD / BM), GT>>>(
            Ap, nullptr, 0, wcat + DMODEL * QKVW, bcat + QKVW, qkv_p, QKVW, NPRD, QKVW, DMODEL,
            nullptr, nullptr, nullptr);

        // rel 0: user -> product (dst = product)
        k_attend<<<(NPRD * 32 + 255) / 256, 256>>>(
            qkv_p, qkv_u, off_p, csr_p, NPRD, prel + (l * 2 + 0) * NH, agg_p);
        // rel 1: product -> user (dst = user)
        k_attend<<<(NUSR * 32 + 255) / 256, 256>>>(
            qkv_u, qkv_p, off_u, csr_u, NUSR, prel + (l * 2 + 1) * NH, agg_u);

        // out GEMM product (dst_t = 1)
        float* Cp = (l == 0) ? xp : out_xp;
        const float* Xop = (l == 0) ? x_product : xp;
        k_gemm<<<dim3(DMODEL / BN, NPRD / BM), GT>>>(
            agg_p, nullptr, 1,
            Wout + (size_t)(l * 2 + 1) * DMODEL * DMODEL, bout + (l * 2 + 1) * DMODEL,
            Cp, DMODEL, NPRD, DMODEL, DMODEL,
            Xop, nullptr, skip + (l * 2 + 1));

        // out GEMM user (dst_t = 0)
        float* Cu = (l == 0) ? xu : out_xu;
        const float* Xou = (l == 0) ? user_emb : xu;
        const int*   rmo = (l == 0) ? user_ids : nullptr;
        k_gemm<<<dim3(DMODEL / BN, NUSR / BM), GT>>>(
            agg_u, nullptr, 1,
            Wout + (size_t)(l * 2 + 0) * DMODEL * DMODEL, bout + (l * 2 + 0) * DMODEL,
            Cu, DMODEL, NUSR, DMODEL, DMODEL,
            Xou, rmo, skip + (l * 2 + 0));

        if (l == 0) {
            k_gelu_inplace<<<2048, 256>>>(xu, NUSR * DMODEL);
            k_gelu_inplace<<<2048, 256>>>(xp, NPRD * DMODEL);
        }
    }
}

// round 8
// speedup vs baseline: 2.7500x; 1.4138x over previous
#include <cuda_runtime.h>
#include <cuda_bf16.h>
#include <cstdint>
#include <math.h>

#define NUSR 80000
#define NPRD 40000
#define NE   160000
#define DMODEL 256
#define NH 4
#define HD 64
#define QKVW 768   // [q | kt | vt]

// ---------------- scratch (static device arrays; no allocation) ----------------
__device__ float g_qkv_u[(size_t)NUSR * QKVW];
__device__ float g_qkv_p[(size_t)NPRD * QKVW];
__device__ float g_xu[(size_t)NUSR * DMODEL];
__device__ float g_xp[(size_t)NPRD * DMODEL];
__device__ float g_agg_u[(size_t)NUSR * DMODEL];
__device__ float g_agg_p[(size_t)NPRD * DMODEL];
__device__ float g_elog[(size_t)NE * NH];
__device__ int   g_csr_p[NE];
__device__ int   g_csr_u[NE];
__device__ int   g_deg_p[NPRD];
__device__ int   g_deg_u[NUSR];
__device__ int   g_off_p[NPRD + 1];
__device__ int   g_off_u[NUSR + 1];
__device__ int   g_cur_p[NPRD];
__device__ int   g_cur_u[NUSR];
__device__ int   g_bsum[256];
// split-bf16 weights, transposed to [N][K] (K-major rows for the mma B operand)
__device__ __align__(16) __nv_bfloat16 g_wbh[2][(size_t)QKVW * DMODEL];
__device__ __align__(16) __nv_bfloat16 g_wbl[2][(size_t)QKVW * DMODEL];
__device__ __align__(16) __nv_bfloat16 g_woh[4][(size_t)DMODEL * DMODEL];
__device__ __align__(16) __nv_bfloat16 g_wol[4][(size_t)DMODEL * DMODEL];
__device__ float g_bcat[2][QKVW];

__device__ __forceinline__ float geluf(float x) { return x * normcdff(x); }

__device__ __forceinline__ uint32_t smem_u32(const void* p) {
    uint32_t a;
    asm("{ .reg .u64 t; cvta.to.shared.u64 t, %1; cvt.u32.u64 %0, t; }" : "=r"(a) : "l"(p));
    return a;
}
__device__ __forceinline__ void ldmx4(uint32_t* r, uint32_t addr) {
    asm volatile("ldmatrix.sync.aligned.m8n8.x4.shared.b16 {%0,%1,%2,%3}, [%4];"
                 : "=r"(r[0]), "=r"(r[1]), "=r"(r[2]), "=r"(r[3]) : "r"(addr));
}
__device__ __forceinline__ void mma16816(float* c, const uint32_t* a, const uint32_t* b) {
    asm volatile(
        "mma.sync.aligned.m16n8k16.row.col.f32.bf16.bf16.f32 "
        "{%0,%1,%2,%3}, {%4,%5,%6,%7}, {%8,%9}, {%0,%1,%2,%3};"
        : "+f"(c[0]), "+f"(c[1]), "+f"(c[2]), "+f"(c[3])
        : "r"(a[0]), "r"(a[1]), "r"(a[2]), "r"(a[3]), "r"(b[0]), "r"(b[1]));
}

// ---------------- CSR build ----------------
__global__ void k_zero_csr() {
    int i = blockIdx.x * blockDim.x + threadIdx.x;
    int st = gridDim.x * blockDim.x;
    for (int j = i; j < NUSR; j += st) { g_deg_u[j] = 0; g_cur_u[j] = 0; }
    for (int j = i; j < NPRD; j += st) { g_deg_p[j] = 0; g_cur_p[j] = 0; }
}

__global__ void k_hist(const int* __restrict__ esrc, const int* __restrict__ edst) {
    int i = blockIdx.x * blockDim.x + threadIdx.x;
    if (i < NE) {
        atomicAdd(&g_deg_p[edst[i]], 1);
        atomicAdd(&g_deg_u[esrc[i]], 1);
    }
}

#define SCH 1024
__global__ void k_bsum(const int* __restrict__ in, int n, int* __restrict__ bsum) {
    __shared__ int sh[256];
    int b = blockIdx.x, t = threadIdx.x;
    int base = b * SCH + t * 4;
    int s = 0;
    #pragma unroll
    for (int j = 0; j < 4; j++) { int i = base + j; if (i < n) s += in[i]; }
    sh[t] = s; __syncthreads();
    #pragma unroll
    for (int off = 128; off; off >>= 1) { if (t < off) sh[t] += sh[t + off]; __syncthreads(); }
    if (t == 0) bsum[b] = sh[0];
}

__global__ void k_scan_bsum(int* __restrict__ bsum, int nb) {
    __shared__ int sh[256];
    int t = threadIdx.x;
    int v = (t < nb) ? bsum[t] : 0;
    sh[t] = v; __syncthreads();
    for (int off = 1; off < 256; off <<= 1) {
        int u = (t >= off) ? sh[t - off] : 0; __syncthreads();
        sh[t] += u; __syncthreads();
    }
    if (t < nb) bsum[t] = sh[t] - v;
}

__global__ void k_scan_out(const int* __restrict__ in, int n, const int* __restrict__ bsum,
                           int* __restrict__ out) {
    __shared__ int sh[256];
    int b = blockIdx.x, t = threadIdx.x;
    int base = b * SCH + t * 4;
    int v[4]; int s = 0;
    #pragma unroll
    for (int j = 0; j < 4; j++) { int i = base + j; v[j] = (i < n) ? in[i] : 0; s += v[j]; }
    sh[t] = s; __syncthreads();
    int mine = s;
    for (int off = 1; off < 256; off <<= 1) {
        int u = (t >= off) ? sh[t - off] : 0; __syncthreads();
        sh[t] += u; __syncthreads();
    }
    int run = bsum[b] + sh[t] - mine;
    #pragma unroll
    for (int j = 0; j < 4; j++) { int i = base + j; if (i < n) out[i] = run; run += v[j]; }
    if (b == 0 && t == 0) out[n] = NE;
}

__global__ void k_scatter(const int* __restrict__ esrc, const int* __restrict__ edst) {
    int i = blockIdx.x * blockDim.x + threadIdx.x;
    if (i >= NE) return;
    int s = esrc[i], d = edst[i];
    int pp = g_off_p[d] + atomicAdd(&g_cur_p[d], 1);
    g_csr_p[pp] = s;
    int pu = g_off_u[s] + atomicAdd(&g_cur_u[s], 1);
    g_csr_u[pu] = d;
}

// ---------------- fused weight build: [Wq | Wk@arel | Wv@mrel], transposed [N][K], bf16-split ----------------
__global__ void k_fuse(const float* __restrict__ Wq, const float* __restrict__ bq,
                       const float* __restrict__ Wk, const float* __restrict__ bk,
                       const float* __restrict__ Wv, const float* __restrict__ bv,
                       const float* __restrict__ arel, const float* __restrict__ mrel, int l) {
    int tot = 2 * 257 * QKVW;
    for (int idx = blockIdx.x * blockDim.x + threadIdx.x; idx < tot; idx += gridDim.x * blockDim.x) {
        int t = idx / (257 * QKVW);
        int r = idx % (257 * QKVW);
        int i = r / QKVW;     // k-row (256 = bias)
        int j = r % QKVW;     // n-col
        int lt = l * 2 + t;
        float out;
        if (j < 256) {
            out = (i < 256) ? Wq[((size_t)(lt * 256 + i)) * 256 + j] : bq[lt * 256 + j];
        } else {
            int jj = j - 256;
            const float *W, *bb, *rel;
            if (jj < 256) { W = Wk; bb = bk; rel = arel; }
            else { jj -= 256; W = Wv; bb = bv; rel = mrel; }
            int h = jj / HD, ee = jj % HD;
            const float* rp = rel + ((size_t)(lt * NH + h)) * HD * HD + ee;
            float s = 0.f;
            if (i < 256) {
                const float* wp = W + ((size_t)(lt * 256 + i)) * 256 + h * HD;
                #pragma unroll 8
                for (int d = 0; d < HD; d++) s += wp[d] * rp[d * HD];
            } else {
                const float* bp = bb + lt * 256 + h * HD;
                #pragma unroll 8
                for (int d = 0; d < HD; d++) s += bp[d] * rp[d * HD];
            }
            out = s;
        }
        if (i < 256) {
            __nv_bfloat16 h16 = __float2bfloat16_rn(out);
            g_wbh[t][(size_t)j * DMODEL + i] = h16;
            g_wbl[t][(size_t)j * DMODEL + i] = __float2bfloat16_rn(out - __bfloat162float(h16));
        } else {
            g_bcat[t][j] = out;
        }
    }
}

// Wout -> transposed [N][K] bf16 hi/lo (all 4 layer/type combos)
__global__ void k_wout(const float* __restrict__ Wout) {
    int tot = 4 * 256 * 256;
    for (int idx = blockIdx.x * blockDim.x + threadIdx.x; idx < tot; idx += gridDim.x * blockDim.x) {
        int lt = idx >> 16;
        int r = idx & 65535;
        int n = r >> 8, k = r & 255;
        float w = Wout[((size_t)lt * 256 + k) * 256 + n];
        __nv_bfloat16 h16 = __float2bfloat16_rn(w);
        g_woh[lt][(size_t)n * 256 + k] = h16;
        g_wol[lt][(size_t)n * 256 + k] = __float2bfloat16_rn(w - __bfloat162float(h16));
    }
}

// ---------------- mma.sync split-bf16 GEMM: C[M,*] = A[M,256] @ B^T, tile 128x64 ----------------
// smem: A tiles hi/lo (128 rows x 32 k bf16, 80B pitch), B tiles hi/lo (64 x 32, 80B pitch)
// epilogue staging reuses the same buffer: 8 warps x (32 x 36 floats)
#define SMA_H 0
#define SMA_L 10240
#define SMB_H 20480
#define SMB_L 25600
#define SM_BYTES 36864

__global__ __launch_bounds__(256)
void k_mgemm(const float* __restrict__ A, const int* __restrict__ rowmap, int geluA,
             const __nv_bfloat16* __restrict__ Bh, const __nv_bfloat16* __restrict__ Bl,
             const float* __restrict__ bias, float* __restrict__ C, int ldc, int M,
             const float* __restrict__ Xold, const int* __restrict__ rowmapOld,
             const float* __restrict__ skipPtr, int geluOut)
{
    __shared__ __align__(16) char sm[SM_BYTES];
    uint32_t sbase = smem_u32(sm);
    int tid = threadIdx.x;
    int lane = tid & 31;
    int wid = tid >> 5;
    int wm = wid >> 1, wn = wid & 1;          // warp grid 4(M) x 2(N)
    int row0 = blockIdx.y * 128;
    int col0 = blockIdx.x * 64;

    // A global load mapping: thread -> (row, 16-k half); 4 float4 per chunk
    int rA = tid >> 1, half = tid & 1;
    int gr = row0 + rA; if (gr > M - 1) gr = M - 1;
    if (rowmap) gr = rowmap[gr];
    const float* pA = A + (size_t)gr * 256 + half * 16;

    // B global load mapping: thread -> (n-row, 8-k quad); 1 uint4 (hi) + 1 uint4 (lo) per chunk
    int rB = tid >> 2, qB = tid & 3;
    const __nv_bfloat16* pBh = Bh + (size_t)(col0 + rB) * 256 + qB * 8;
    const __nv_bfloat16* pBl = Bl + (size_t)(col0 + rB) * 256 + qB * 8;

    float c[2][4][4];
    #pragma unroll
    for (int i = 0; i < 2; i++)
        #pragma unroll
        for (int j = 0; j < 4; j++)
            #pragma unroll
            for (int k = 0; k < 4; k++) c[i][j][k] = 0.f;

    float4 av[4];
    uint4 bhv, blv;
    // prefetch chunk 0
    #pragma unroll
    for (int j = 0; j < 4; j++) av[j] = *(const float4*)(pA + j * 4);
    bhv = *(const uint4*)pBh;
    blv = *(const uint4*)pBl;

    // precompute ldmatrix smem addresses (bytes)
    int a_krow = ((lane >> 4) << 3);                 // 0 or 8 (k offset within 16)
    int a_row_base = wm * 32 + ((lane >> 3) & 1) * 8 + (lane & 7);
    int b_nrow = wn * 32 + ((lane >> 4) << 3) + (lane & 7);  // tile>>1 selects n+8
    int b_kcol = ((lane >> 3) & 1) * 8;                       // tile&1 selects k+8

    for (int ch = 0; ch < 8; ch++) {
        // ---- convert + store A (hi/lo bf16) ----
        {
            uint32_t h[8], l[8];
            #pragma unroll
            for (int j = 0; j < 4; j++) {
                float4 v = av[j];
                if (geluA) { v.x = geluf(v.x); v.y = geluf(v.y); v.z = geluf(v.z); v.w = geluf(v.w); }
                __nv_bfloat162 h01 = __floats2bfloat162_rn(v.x, v.y);
                __nv_bfloat162 h23 = __floats2bfloat162_rn(v.z, v.w);
                float r0 = v.x - __bfloat162float(__low2bfloat16(h01));
                float r1 = v.y - __bfloat162float(__high2bfloat16(h01));
                float r2 = v.z - __bfloat162float(__low2bfloat16(h23));
                float r3 = v.w - __bfloat162float(__high2bfloat16(h23));
                __nv_bfloat162 l01 = __floats2bfloat162_rn(r0, r1);
                __nv_bfloat162 l23 = __floats2bfloat162_rn(r2, r3);
                h[j * 2 + 0] = *(uint32_t*)&h01; h[j * 2 + 1] = *(uint32_t*)&h23;
                l[j * 2 + 0] = *(uint32_t*)&l01; l[j * 2 + 1] = *(uint32_t*)&l23;
            }
            char* aB = sm + SMA_H + rA * 80 + half * 32;
            ((uint4*)aB)[0] = make_uint4(h[0], h[1], h[2], h[3]);
            ((uint4*)(aB + 16))[0] = make_uint4(h[4], h[5], h[6], h[7]);
            char* aL = sm + SMA_L + rA * 80 + half * 32;
            ((uint4*)aL)[0] = make_uint4(l[0], l[1], l[2], l[3]);
            ((uint4*)(aL + 16))[0] = make_uint4(l[4], l[5], l[6], l[7]);
            *(uint4*)(sm + SMB_H + rB * 80 + qB * 16) = bhv;
            *(uint4*)(sm + SMB_L + rB * 80 + qB * 16) = blv;
        }
        __syncthreads();

        // ---- prefetch next chunk ----
        if (ch < 7) {
            int k0 = (ch + 1) * 32;
            #pragma unroll
            for (int j = 0; j < 4; j++) av[j] = *(const float4*)(pA + k0 + j * 4);
            bhv = *(const uint4*)(pBh + k0);
            blv = *(const uint4*)(pBl + k0);
        }

        // ---- compute chunk: 2 k16 steps ----
        #pragma unroll
        for (int ks = 0; ks < 2; ks++) {
            int kbase = ks * 16;
            uint32_t ah[2][4], al[2][4], bh[4][2], bl[4][2];
            #pragma unroll
            for (int mt = 0; mt < 2; mt++) {
                int row = a_row_base + mt * 16;
                uint32_t ad = sbase + SMA_H + row * 80 + (kbase + a_krow) * 2;
                ldmx4(ah[mt], ad);
                ldmx4(al[mt], ad + (SMA_L - SMA_H));
            }
            #pragma unroll
            for (int bt = 0; bt < 2; bt++) {
                int nrow = b_nrow + bt * 16;
                uint32_t bd = sbase + SMB_H + nrow * 80 + (kbase + b_kcol) * 2;
                uint32_t tmp[4];
                ldmx4(tmp, bd);
                bh[bt * 2 + 0][0] = tmp[0]; bh[bt * 2 + 0][1] = tmp[1];
                bh[bt * 2 + 1][0] = tmp[2]; bh[bt * 2 + 1][1] = tmp[3];
                ldmx4(tmp, bd + (SMB_L - SMB_H));
                bl[bt * 2 + 0][0] = tmp[0]; bl[bt * 2 + 0][1] = tmp[1];
                bl[bt * 2 + 1][0] = tmp[2]; bl[bt * 2 + 1][1] = tmp[3];
            }
            #pragma unroll
            for (int mt = 0; mt < 2; mt++)
                #pragma unroll
                for (int nt = 0; nt < 4; nt++) {
                    mma16816(c[mt][nt], ah[mt], bh[nt]);
                    mma16816(c[mt][nt], ah[mt], bl[nt]);
                    mma16816(c[mt][nt], al[mt], bh[nt]);
                }
        }
        __syncthreads();
    }

    // ---- epilogue: frags -> padded smem stage -> coalesced stores ----
    float beta = 0.f, ombeta = 0.f;
    if (skipPtr) { float sk = *skipPtr; beta = 1.f / (1.f + expf(-sk)); ombeta = 1.f - beta; }

    float* wst = (float*)sm + wid * 1152;   // 32 rows x 36 floats per warp
    #pragma unroll
    for (int mt = 0; mt < 2; mt++)
        #pragma unroll
        for (int nt = 0; nt < 4; nt++) {
            int r = mt * 16 + (lane >> 2);
            int cc = nt * 8 + (lane & 3) * 2;
            wst[r * 36 + cc] = c[mt][nt][0];
            wst[r * 36 + cc + 1] = c[mt][nt][1];
            wst[(r + 8) * 36 + cc] = c[mt][nt][2];
            wst[(r + 8) * 36 + cc + 1] = c[mt][nt][3];
        }
    __syncwarp();

    int colg = col0 + wn * 32 + (lane & 7) * 4;
    float4 bi = *(const float4*)(bias + colg);
    #pragma unroll
    for (int rr = 0; rr < 8; rr++) {
        int r = rr * 4 + (lane >> 3);
        int grow = row0 + wm * 32 + r;
        if (grow < M) {
            float4 v = *(float4*)&wst[r * 36 + (lane & 7) * 4];
            v.x += bi.x; v.y += bi.y; v.z += bi.z; v.w += bi.w;
            if (skipPtr) {
                int ro = rowmapOld ? rowmapOld[grow] : grow;
                float4 xo = *(const float4*)(Xold + (size_t)ro * 256 + colg);
                v.x = beta * v.x + ombeta * xo.x;
                v.y = beta * v.y + ombeta * xo.y;
                v.z = beta * v.z + ombeta * xo.z;
                v.w = beta * v.w + ombeta * xo.w;
            }
            if (geluOut) { v.x = geluf(v.x); v.y = geluf(v.y); v.z = geluf(v.z); v.w = geluf(v.w); }
            *(float4*)(C + (size_t)grow * ldc + colg) = v;
        }
    }
}

// ---------------- per-dst-node attention (one warp per node, no atomics) ----------------
__global__ void k_attend(const float* __restrict__ qkv_dst, const float* __restrict__ qkv_src,
                         const int* __restrict__ offs, const int* __restrict__ csr,
                         int n, const float* __restrict__ prelp, float* __restrict__ agg)
{
    int warp = (blockIdx.x * blockDim.x + threadIdx.x) >> 5;
    int lane = threadIdx.x & 31;
    if (warp >= n) return;

    const float* q = qkv_dst + (size_t)warp * QKVW;
    float qv[8];
    #pragma unroll
    for (int k = 0; k < 8; k++) qv[k] = q[lane + 32 * k];

    const float inv_sqrt_d = 0.125f;
    float pr0 = prelp[0] * inv_sqrt_d, pr1 = prelp[1] * inv_sqrt_d;
    float pr2 = prelp[2] * inv_sqrt_d, pr3 = prelp[3] * inv_sqrt_d;

    int beg = offs[warp], end = offs[warp + 1];
    float m0 = -1e30f, m1 = -1e30f, m2 = -1e30f, m3 = -1e30f;

    for (int e = beg; e < end; e++) {
        int s = csr[e];
        const float* kt = qkv_src + (size_t)s * QKVW + 256;
        float p0 = 0.f, p1 = 0.f, p2 = 0.f, p3 = 0.f;
        #pragma unroll
        for (int k = 0; k < 8; k++) {
            float t = qv[k] * kt[lane + 32 * k];
            if (k < 2) p0 += t; else if (k < 4) p1 += t; else if (k < 6) p2 += t; else p3 += t;
        }
        #pragma unroll
        for (int off = 16; off; off >>= 1) {
            p0 += __shfl_xor_sync(0xffffffffu, p0, off);
            p1 += __shfl_xor_sync(0xffffffffu, p1, off);
            p2 += __shfl_xor_sync(0xffffffffu, p2, off);
            p3 += __shfl_xor_sync(0xffffffffu, p3, off);
        }
        p0 *= pr0; p1 *= pr1; p2 *= pr2; p3 *= pr3;
        m0 = fmaxf(m0, p0); m1 = fmaxf(m1, p1);
        m2 = fmaxf(m2, p2); m3 = fmaxf(m3, p3);
        if (lane == 0) *(float4*)&g_elog[(size_t)e * 4] = make_float4(p0, p1, p2, p3);
    }

    float s0 = 0.f, s1 = 0.f, s2 = 0.f, s3 = 0.f;
    float acc[8] = {0.f, 0.f, 0.f, 0.f, 0.f, 0.f, 0.f, 0.f};
    for (int e = beg; e < end; e++) {
        int s = csr[e];
        float4 lg = *(const float4*)&g_elog[(size_t)e * 4];
        float e0 = __expf(lg.x - m0), e1 = __expf(lg.y - m1);
        float e2 = __expf(lg.z - m2), e3 = __expf(lg.w - m3);
        s0 += e0; s1 += e1; s2 += e2; s3 += e3;
        const float* vt = qkv_src + (size_t)s * QKVW + 512;
        #pragma unroll
        for (int k = 0; k < 8; k++) {
            float ee = (k < 2) ? e0 : (k < 4) ? e1 : (k < 6) ? e2 : e3;
            acc[k] = fmaf(ee, vt[lane + 32 * k], acc[k]);
        }
    }
    float i0 = 1.f / (s0 + 1e-16f), i1 = 1.f / (s1 + 1e-16f);
    float i2 = 1.f / (s2 + 1e-16f), i3 = 1.f / (s3 + 1e-16f);
    float* o = agg + (size_t)warp * DMODEL;
    #pragma unroll
    for (int k = 0; k < 8; k++) {
        float inv = (k < 2) ? i0 : (k < 4) ? i1 : (k < 6) ? i2 : i3;
        o[lane + 32 * k] = acc[k] * inv;
    }
}

// ---------------- host orchestration ----------------
extern "C" void kernel_launch(void* const* d_in, const int* in_sizes, int n_in,
                              void* d_out, int out_size) {
    const int*   user_ids  = (const int*)d_in[0];
    const float* x_product = (const float*)d_in[1];
    const int*   edge_src  = (const int*)d_in[2];
    const int*   edge_dst  = (const int*)d_in[3];
    const float* user_emb  = (const float*)d_in[4];
    const float* Wk   = (const float*)d_in[5];
    const float* bk   = (const float*)d_in[6];
    const float* Wq   = (const float*)d_in[7];
    const float* bq   = (const float*)d_in[8];
    const float* Wv   = (const float*)d_in[9];
    const float* bv   = (const float*)d_in[10];
    const float* Wout = (const float*)d_in[11];
    const float* bout = (const float*)d_in[12];
    const float* skip = (const float*)d_in[13];
    const float* arel = (const float*)d_in[14];
    const float* mrel = (const float*)d_in[15];
    const float* prel = (const float*)d_in[16];

    float* out_xu = (float*)d_out;
    float* out_xp = out_xu + (size_t)NUSR * DMODEL;

    float *qkv_u, *qkv_p, *xu, *xp, *agg_u, *agg_p, *bcat;
    __nv_bfloat16 *wbh, *wbl, *woh, *wol;
    int *csr_p, *csr_u, *off_p, *off_u, *deg_p, *deg_u, *bsum;
    cudaGetSymbolAddress((void**)&qkv_u, g_qkv_u);
    cudaGetSymbolAddress((void**)&qkv_p, g_qkv_p);
    cudaGetSymbolAddress((void**)&xu, g_xu);
    cudaGetSymbolAddress((void**)&xp, g_xp);
    cudaGetSymbolAddress((void**)&agg_u, g_agg_u);
    cudaGetSymbolAddress((void**)&agg_p, g_agg_p);
    cudaGetSymbolAddress((void**)&bcat, g_bcat);
    cudaGetSymbolAddress((void**)&wbh, g_wbh);
    cudaGetSymbolAddress((void**)&wbl, g_wbl);
    cudaGetSymbolAddress((void**)&woh, g_woh);
    cudaGetSymbolAddress((void**)&wol, g_wol);
    cudaGetSymbolAddress((void**)&csr_p, g_csr_p);
    cudaGetSymbolAddress((void**)&csr_u, g_csr_u);
    cudaGetSymbolAddress((void**)&off_p, g_off_p);
    cudaGetSymbolAddress((void**)&off_u, g_off_u);
    cudaGetSymbolAddress((void**)&deg_p, g_deg_p);
    cudaGetSymbolAddress((void**)&deg_u, g_deg_u);
    cudaGetSymbolAddress((void**)&bsum, g_bsum);

    // ---- CSR build ----
    k_zero_csr<<<256, 256>>>();
    k_hist<<<(NE + 255) / 256, 256>>>(edge_src, edge_dst);
    int nbP = (NPRD + SCH - 1) / SCH, nbU = (NUSR + SCH - 1) / SCH;
    k_bsum<<<nbP, 256>>>(deg_p, NPRD, bsum);
    k_scan_bsum<<<1, 256>>>(bsum, nbP);
    k_scan_out<<<nbP, 256>>>(deg_p, NPRD, bsum, off_p);
    k_bsum<<<nbU, 256>>>(deg_u, NUSR, bsum);
    k_scan_bsum<<<1, 256>>>(bsum, nbU);
    k_scan_out<<<nbU, 256>>>(deg_u, NUSR, bsum, off_u);
    k_scatter<<<(NE + 255) / 256, 256>>>(edge_src, edge_dst);

    k_wout<<<512, 256>>>(Wout);

    int mtU = (NUSR + 127) / 128;   // 625
    int mtP = (NPRD + 127) / 128;   // 313

    for (int l = 0; l < 2; l++) {
        k_fuse<<<1024, 256>>>(Wq, bq, Wk, bk, Wv, bv, arel, mrel, l);

        const float* Au  = (l == 0) ? user_emb : xu;
        const int*   rmu = (l == 0) ? user_ids : nullptr;
        k_mgemm<<<dim3(QKVW / 64, mtU), 256>>>(
            Au, rmu, 0, wbh, wbl, bcat, qkv_u, QKVW, NUSR,
            nullptr, nullptr, nullptr, 0);

        const float* Ap = (l == 0) ? x_product : xp;
        k_mgemm<<<dim3(QKVW / 64, mtP), 256>>>(
            Ap, nullptr, 0, wbh + (size_t)QKVW * DMODEL, wbl + (size_t)QKVW * DMODEL,
            bcat + QKVW, qkv_p, QKVW, NPRD,
            nullptr, nullptr, nullptr, 0);

        k_attend<<<(NPRD * 32 + 255) / 256, 256>>>(
            qkv_p, qkv_u, off_p, csr_p, NPRD, prel + (l * 2 + 0) * NH, agg_p);
        k_attend<<<(NUSR * 32 + 255) / 256, 256>>>(
            qkv_u, qkv_p, off_u, csr_u, NUSR, prel + (l * 2 + 1) * NH, agg_u);

        // out GEMM product (dst_t = 1)
        float* Cp = (l == 0) ? xp : out_xp;
        const float* Xop = (l == 0) ? x_product : xp;
        k_mgemm<<<dim3(DMODEL / 64, mtP), 256>>>(
            agg_p, nullptr, 1,
            woh + (size_t)(l * 2 + 1) * DMODEL * DMODEL, wol + (size_t)(l * 2 + 1) * DMODEL * DMODEL,
            bout + (l * 2 + 1) * DMODEL, Cp, DMODEL, NPRD,
            Xop, nullptr, skip + (l * 2 + 1), (l == 0) ? 1 : 0);

        // out GEMM user (dst_t = 0)
        float* Cu = (l == 0) ? xu : out_xu;
        const float* Xou = (l == 0) ? user_emb : xu;
        const int*   rmo = (l == 0) ? user_ids : nullptr;
        k_mgemm<<<dim3(DMODEL / 64, mtU), 256>>>(
            agg_u, nullptr, 1,
            woh + (size_t)(l * 2 + 0) * DMODEL * DMODEL, wol + (size_t)(l * 2 + 0) * DMODEL * DMODEL,
            bout + (l * 2 + 0) * DMODEL, Cu, DMODEL, NUSR,
            Xou, rmo, skip + (l * 2 + 0), (l == 0) ? 1 : 0);
    }
}